// round 1
// baseline (speedup 1.0000x reference)
#include <cuda_runtime.h>
#include <cstdint>

#define BDIM   2
#define LSEQ   1024
#define DMODEL 1024
#define DINCH  2048
#define DSTATE 16
#define DCONV  4
#define DTRANK 64
#define MROWS  (BDIM * LSEQ)   // 2048
#define XDBL_W (DTRANK + 2 * DSTATE)   // 96

// ---------------- scratch (static device arrays; no allocation) ----------------
__device__ float g_h   [MROWS * DMODEL];       // layernorm out            8 MB
__device__ float g_xz  [MROWS * 2 * DINCH];    // in_proj out             32 MB
__device__ float g_xc  [MROWS * DINCH];        // conv+silu out           16 MB
__device__ float g_xdbl[MROWS * XDBL_W];       // x_proj out             0.75 MB
__device__ float g_dt  [MROWS * DINCH];        // softplus(dt_proj)       16 MB
__device__ float g_y   [MROWS * DINCH];        // scan out (gated)        16 MB

// ---------------- layernorm ----------------
__global__ void layernorm_kernel(const float* __restrict__ x,
                                 const float* __restrict__ w,
                                 const float* __restrict__ b,
                                 float* __restrict__ out) {
    int row = blockIdx.x;
    int t = threadIdx.x;  // 256 threads, 4 floats each
    const float4* xr = reinterpret_cast<const float4*>(x + (size_t)row * DMODEL);
    float4 v = xr[t];
    float s  = v.x + v.y + v.z + v.w;
    float s2 = v.x*v.x + v.y*v.y + v.z*v.z + v.w*v.w;
    #pragma unroll
    for (int o = 16; o; o >>= 1) {
        s  += __shfl_xor_sync(0xffffffffu, s,  o);
        s2 += __shfl_xor_sync(0xffffffffu, s2, o);
    }
    __shared__ float sh[2][8];
    int wid = t >> 5, lid = t & 31;
    if (lid == 0) { sh[0][wid] = s; sh[1][wid] = s2; }
    __syncthreads();
    s = 0.f; s2 = 0.f;
    #pragma unroll
    for (int i = 0; i < 8; i++) { s += sh[0][i]; s2 += sh[1][i]; }
    float mu  = s * (1.f / DMODEL);
    float var = s2 * (1.f / DMODEL) - mu * mu;
    float inv = rsqrtf(var + 1e-5f);
    float4 wv = reinterpret_cast<const float4*>(w)[t];
    float4 bv = reinterpret_cast<const float4*>(b)[t];
    float4 o;
    o.x = (v.x - mu) * inv * wv.x + bv.x;
    o.y = (v.y - mu) * inv * wv.y + bv.y;
    o.z = (v.z - mu) * inv * wv.z + bv.z;
    o.w = (v.w - mu) * inv * wv.w + bv.w;
    reinterpret_cast<float4*>(out + (size_t)row * DMODEL)[t] = o;
}

// ---------------- SGEMM: C[M,N] = act(A[M,K(lda)] * W[N,K]^T + bias) + res ----------------
__device__ __forceinline__ float softplus_f(float x) {
    return (x > 20.f) ? x : log1pf(__expf(x));
}

template<int ACT, bool BIAS, bool RES>
__global__ void __launch_bounds__(256, 2) sgemm_kernel(
    const float* __restrict__ A, int lda,
    const float* __restrict__ W,
    const float* __restrict__ bias,
    const float* __restrict__ res,
    float* __restrict__ C,
    int M, int N, int K)
{
    constexpr int BM = 128, BN = 128, BK = 8;
    __shared__ float As[BK][BM];
    __shared__ float Bs[BK][BN];
    int tid = threadIdx.x;
    int bm = blockIdx.y * BM, bn = blockIdx.x * BN;
    int lrow = tid >> 1;
    int lcol = (tid & 1) * 4;
    int tm = (tid >> 4) * 8;
    int tn = (tid & 15) * 8;
    float acc[8][8];
    #pragma unroll
    for (int i = 0; i < 8; i++)
        #pragma unroll
        for (int j = 0; j < 8; j++) acc[i][j] = 0.f;

    const float* Aptr = A + (size_t)(bm + lrow) * lda + lcol;
    const float* Wptr = W + (size_t)(bn + lrow) * K + lcol;
    bool aok = (bm + lrow) < M;
    bool wok = (bn + lrow) < N;

    for (int k0 = 0; k0 < K; k0 += BK) {
        float4 av = make_float4(0.f, 0.f, 0.f, 0.f);
        float4 wv = make_float4(0.f, 0.f, 0.f, 0.f);
        if (aok) av = *reinterpret_cast<const float4*>(Aptr + k0);
        if (wok) wv = *reinterpret_cast<const float4*>(Wptr + k0);
        As[lcol + 0][lrow] = av.x; As[lcol + 1][lrow] = av.y;
        As[lcol + 2][lrow] = av.z; As[lcol + 3][lrow] = av.w;
        Bs[lcol + 0][lrow] = wv.x; Bs[lcol + 1][lrow] = wv.y;
        Bs[lcol + 2][lrow] = wv.z; Bs[lcol + 3][lrow] = wv.w;
        __syncthreads();
        #pragma unroll
        for (int kk = 0; kk < BK; kk++) {
            float4 a0 = *reinterpret_cast<const float4*>(&As[kk][tm]);
            float4 a1 = *reinterpret_cast<const float4*>(&As[kk][tm + 4]);
            float4 b0 = *reinterpret_cast<const float4*>(&Bs[kk][tn]);
            float4 b1 = *reinterpret_cast<const float4*>(&Bs[kk][tn + 4]);
            float ar[8] = {a0.x, a0.y, a0.z, a0.w, a1.x, a1.y, a1.z, a1.w};
            float br[8] = {b0.x, b0.y, b0.z, b0.w, b1.x, b1.y, b1.z, b1.w};
            #pragma unroll
            for (int i = 0; i < 8; i++)
                #pragma unroll
                for (int j = 0; j < 8; j++)
                    acc[i][j] = fmaf(ar[i], br[j], acc[i][j]);
        }
        __syncthreads();
    }

    #pragma unroll
    for (int i = 0; i < 8; i++) {
        int m = bm + tm + i;
        if (m >= M) continue;
        #pragma unroll
        for (int j = 0; j < 8; j++) {
            int nn = bn + tn + j;
            if (nn >= N) continue;
            float v = acc[i][j];
            if (BIAS) v += bias[nn];
            if (ACT == 1) v = softplus_f(v);
            if (RES) v += res[(size_t)m * N + nn];
            C[(size_t)m * N + nn] = v;
        }
    }
}

// ---------------- causal depthwise conv (k=4) + silu ----------------
__global__ void conv_silu_kernel(const float* __restrict__ xz,
                                 const float* __restrict__ cw,
                                 const float* __restrict__ cb,
                                 float* __restrict__ xc) {
    int idx = blockIdx.x * blockDim.x + threadIdx.x;
    int d = idx & (DINCH - 1);
    int l = (idx >> 11) & (LSEQ - 1);
    int b = idx >> 21;
    float v = cb[d];
    const float* base = xz + ((size_t)b * LSEQ) * 2 * DINCH + d;  // xm = first half
    #pragma unroll
    for (int k = 0; k < DCONV; k++) {
        int li = l - (DCONV - 1) + k;
        if (li >= 0)
            v = fmaf(base[(size_t)li * 2 * DINCH], cw[d * DCONV + k], v);
    }
    v = v / (1.f + __expf(-v));  // silu
    xc[idx] = v;
}

// ---------------- selective scan: thread per (b,d,n) ----------------
__global__ void scan_kernel(const float* __restrict__ dt,
                            const float* __restrict__ xdbl,
                            const float* __restrict__ xc,
                            const float* __restrict__ xz,
                            const float* __restrict__ A_log,
                            const float* __restrict__ D_skip,
                            float* __restrict__ y) {
    int g = blockIdx.x * blockDim.x + threadIdx.x;  // 65536 total
    int n = g & (DSTATE - 1);
    int d = (g >> 4) & (DINCH - 1);
    int b = g >> 15;

    float a   = -__expf(A_log[d * DSTATE + n]);
    float D_d = D_skip[d];
    float h = 0.f;

    const float* dt_p = dt   + (size_t)b * LSEQ * DINCH + d;
    const float* xc_p = xc   + (size_t)b * LSEQ * DINCH + d;
    const float* z_p  = xz   + (size_t)b * LSEQ * 2 * DINCH + DINCH + d;
    const float* B_p  = xdbl + (size_t)b * LSEQ * XDBL_W + DTRANK + n;
    const float* C_p  = B_p + DSTATE;
    float* y_p = y + (size_t)b * LSEQ * DINCH + d;

    // prefetch t = 0
    float dt_v = __ldg(dt_p);
    float xc_v = __ldg(xc_p);
    float Bv   = __ldg(B_p);
    float Cv   = __ldg(C_p);

    for (int t = 0; t < LSEQ; t++) {
        float dt_c = dt_v, xc_c = xc_v, Bc = Bv, Cc = Cv;
        if (t + 1 < LSEQ) {  // prefetch next timestep
            dt_v = __ldg(dt_p + (size_t)(t + 1) * DINCH);
            xc_v = __ldg(xc_p + (size_t)(t + 1) * DINCH);
            Bv   = __ldg(B_p + (size_t)(t + 1) * XDBL_W);
            Cv   = __ldg(C_p + (size_t)(t + 1) * XDBL_W);
        }
        float dA = __expf(dt_c * a);
        h = fmaf(dA, h, dt_c * Bc * xc_c);
        float p = h * Cc;
        p += __shfl_xor_sync(0xffffffffu, p, 8);
        p += __shfl_xor_sync(0xffffffffu, p, 4);
        p += __shfl_xor_sync(0xffffffffu, p, 2);
        p += __shfl_xor_sync(0xffffffffu, p, 1);
        if (n == 0) {
            float zv = __ldg(z_p + (size_t)t * 2 * DINCH);
            float sz = zv / (1.f + __expf(-zv));
            y_p[(size_t)t * DINCH] = (p + xc_c * D_d) * sz;
        }
    }
}

// ---------------- launch ----------------
extern "C" void kernel_launch(void* const* d_in, const int* in_sizes, int n_in,
                              void* d_out, int out_size) {
    const float* x         = (const float*)d_in[0];
    const float* norm_w    = (const float*)d_in[1];
    const float* norm_b    = (const float*)d_in[2];
    const float* in_proj_w = (const float*)d_in[3];
    const float* conv_w    = (const float*)d_in[4];
    const float* conv_b    = (const float*)d_in[5];
    const float* x_proj_w  = (const float*)d_in[6];
    const float* dt_w      = (const float*)d_in[7];
    const float* dt_b      = (const float*)d_in[8];
    const float* A_log     = (const float*)d_in[9];
    const float* D_skip    = (const float*)d_in[10];
    const float* out_w     = (const float*)d_in[11];
    float* out = (float*)d_out;

    static float *p_h = nullptr, *p_xz = nullptr, *p_xc = nullptr,
                 *p_xdbl = nullptr, *p_dt = nullptr, *p_y = nullptr;
    if (!p_h) {
        cudaGetSymbolAddress((void**)&p_h,    g_h);
        cudaGetSymbolAddress((void**)&p_xz,   g_xz);
        cudaGetSymbolAddress((void**)&p_xc,   g_xc);
        cudaGetSymbolAddress((void**)&p_xdbl, g_xdbl);
        cudaGetSymbolAddress((void**)&p_dt,   g_dt);
        cudaGetSymbolAddress((void**)&p_y,    g_y);
    }

    // 1. layernorm
    layernorm_kernel<<<MROWS, 256>>>(x, norm_w, norm_b, p_h);

    // 2. in_proj: [2048,1024] @ [4096,1024]^T -> xz [2048,4096]
    {
        dim3 g(2 * DINCH / 128, MROWS / 128);
        sgemm_kernel<0, false, false><<<g, 256>>>(p_h, DMODEL, in_proj_w,
                                                  nullptr, nullptr, p_xz,
                                                  MROWS, 2 * DINCH, DMODEL);
    }

    // 3. causal depthwise conv + silu
    conv_silu_kernel<<<(MROWS * DINCH) / 256, 256>>>(p_xz, conv_w, conv_b, p_xc);

    // 4. x_proj: [2048,2048] @ [96,2048]^T -> x_dbl [2048,96]
    {
        dim3 g((XDBL_W + 127) / 128, MROWS / 128);
        sgemm_kernel<0, false, false><<<g, 256>>>(p_xc, DINCH, x_proj_w,
                                                  nullptr, nullptr, p_xdbl,
                                                  MROWS, XDBL_W, DINCH);
    }

    // 5. dt_proj + softplus: x_dbl[:, :64] @ [2048,64]^T + b -> dt [2048,2048]
    {
        dim3 g(DINCH / 128, MROWS / 128);
        sgemm_kernel<1, true, false><<<g, 256>>>(p_xdbl, XDBL_W, dt_w,
                                                 dt_b, nullptr, p_dt,
                                                 MROWS, DINCH, DTRANK);
    }

    // 6. selective scan + D skip + z gate
    scan_kernel<<<(BDIM * DINCH * DSTATE) / 256, 256>>>(p_dt, p_xdbl, p_xc,
                                                        p_xz, A_log, D_skip, p_y);

    // 7. out_proj + residual: y @ [1024,2048]^T + x -> out [2048,1024]
    {
        dim3 g(DMODEL / 128, MROWS / 128);
        sgemm_kernel<0, false, true><<<g, 256>>>(p_y, DINCH, out_w,
                                                 nullptr, x, out,
                                                 MROWS, DMODEL, DINCH);
    }
}

// round 3
// speedup vs baseline: 1.9673x; 1.9673x over previous
#include <cuda_runtime.h>
#include <cstdint>

#define BDIM   2
#define LSEQ   1024
#define DMODEL 1024
#define DINCH  2048
#define DSTATE 16
#define DCONV  4
#define DTRANK 64
#define MROWS  (BDIM * LSEQ)          // 2048
#define XDBL_W (DTRANK + 2 * DSTATE)  // 96

// ---------------- scratch (static device arrays; no allocation) ----------------
__device__ float g_h   [MROWS * DMODEL];
__device__ float g_xz  [MROWS * 2 * DINCH];
__device__ float g_xc  [MROWS * DINCH];
__device__ float g_xdbl[MROWS * XDBL_W];
__device__ float g_dt  [MROWS * DINCH];
__device__ float g_y   [MROWS * DINCH];
// tf32-rounded weight copies
__device__ float g_wa  [2 * DINCH * DMODEL];
__device__ float g_wb  [XDBL_W * DINCH];
__device__ float g_wc  [DINCH * DTRANK];
__device__ float g_wd  [DMODEL * DINCH];

// ---------------- helpers ----------------
__device__ __forceinline__ float rna_tf32(float x) {
    uint32_t o; asm("cvt.rna.tf32.f32 %0, %1;" : "=r"(o) : "f"(x));
    return __uint_as_float(o);
}
__device__ __forceinline__ void cp_async16(uint32_t s, const void* g) {
    asm volatile("cp.async.ca.shared.global [%0], [%1], 16;" :: "r"(s), "l"(g));
}
__device__ __forceinline__ void cp_commit() {
    asm volatile("cp.async.commit_group;" ::: "memory");
}
__device__ __forceinline__ void cp_wait1() {
    asm volatile("cp.async.wait_group 1;" ::: "memory");
}
__device__ __forceinline__ float softplus_f(float x) {
    return (x > 20.f) ? x : log1pf(__expf(x));
}
__device__ __forceinline__ void mma_tf32(float& c0, float& c1, float& c2, float& c3,
                                         uint32_t a0, uint32_t a1, uint32_t a2, uint32_t a3,
                                         uint32_t b0, uint32_t b1) {
    asm volatile(
        "mma.sync.aligned.m16n8k8.row.col.f32.tf32.tf32.f32 "
        "{%0,%1,%2,%3}, {%4,%5,%6,%7}, {%8,%9}, {%0,%1,%2,%3};"
        : "+f"(c0), "+f"(c1), "+f"(c2), "+f"(c3)
        : "r"(a0), "r"(a1), "r"(a2), "r"(a3), "r"(b0), "r"(b1));
}

// ---------------- tf32 mma.sync GEMM: C[M,N] = epi(A[M,K] @ W[N,K]^T) ----------------
// 256 threads = 8 warps, warp grid 2(M) x 4(N); warp tile 64 x (BN/4).
// smem per stage: (128 + BN) rows x 36 floats (BK=32 + pad 4).
// EPI: 0 = none, 1 = softplus(v + bias[n]), 2 = v + res[m*ldc+n]
#define SROW 36
template<int BN, int EPI>
__global__ void __launch_bounds__(256, 2) gemm_mma_kernel(
    const float* __restrict__ A, int lda,
    const float* __restrict__ W,
    const float* __restrict__ bias,
    const float* __restrict__ res,
    float* __restrict__ C,
    int ldc, int K)
{
    constexpr int WN = BN / 4;
    constexpr int NFRAG = WN / 8;
    constexpr int STAGE = (128 + BN) * SROW;  // floats

    extern __shared__ float sm[];
    uint32_t sm_u32;
    asm("{ .reg .u64 t; cvta.to.shared.u64 t, %1; cvt.u32.u64 %0, t; }"
        : "=r"(sm_u32) : "l"(sm));

    const int tid = threadIdx.x;
    const int wid = tid >> 5, lane = tid & 31;
    const int warp_m = wid & 1, warp_n = wid >> 1;
    const int bm = blockIdx.y * 128;
    const int bn = blockIdx.x * BN;
    const int niter = K >> 5;

    // load mapping: thread -> (row = tid/8, 16B chunk = tid%8)
    const int lrow = tid >> 3;
    const int lch  = (tid & 7) * 4;   // float offset within 32-col row

    float acc[4][NFRAG][4];
    #pragma unroll
    for (int i = 0; i < 4; i++)
        #pragma unroll
        for (int j = 0; j < NFRAG; j++)
            #pragma unroll
            for (int c = 0; c < 4; c++) acc[i][j][c] = 0.f;

    auto issue_stage = [&](int it, int s) {
        const int k0 = it * 32;
        uint32_t as = sm_u32 + (uint32_t)(s * STAGE) * 4u;
        uint32_t bs = as + 128u * SROW * 4u;
        const float* Ag = A + (size_t)(bm + lrow) * lda + k0 + lch;
        #pragma unroll
        for (int w = 0; w < 4; w++)
            cp_async16(as + ((lrow + 32 * w) * SROW + lch) * 4u,
                       Ag + (size_t)(32 * w) * lda);
        const float* Wg = W + (size_t)(bn + lrow) * K + k0 + lch;
        #pragma unroll
        for (int w = 0; w < BN / 32; w++)
            cp_async16(bs + ((lrow + 32 * w) * SROW + lch) * 4u,
                       Wg + (size_t)(32 * w) * K);
    };

    issue_stage(0, 0);
    cp_commit();

    for (int it = 0; it < niter; it++) {
        if (it + 1 < niter) issue_stage(it + 1, (it + 1) & 1);
        cp_commit();
        cp_wait1();
        __syncthreads();

        const float* as = sm + (it & 1) * STAGE;
        const float* bs = as + 128 * SROW;
        const int r4 = lane >> 2, c4 = lane & 3;

        #pragma unroll
        for (int kk = 0; kk < 4; kk++) {
            const int k0 = kk * 8;
            uint32_t a[4][4];
            #pragma unroll
            for (int mi = 0; mi < 4; mi++) {
                const float* ap = as + (warp_m * 64 + mi * 16 + r4) * SROW + k0 + c4;
                a[mi][0] = __float_as_uint(ap[0]);
                a[mi][1] = __float_as_uint(ap[8 * SROW]);
                a[mi][2] = __float_as_uint(ap[4]);
                a[mi][3] = __float_as_uint(ap[8 * SROW + 4]);
            }
            uint32_t b[NFRAG][2];
            #pragma unroll
            for (int ni = 0; ni < NFRAG; ni++) {
                const float* bp = bs + (warp_n * WN + ni * 8 + r4) * SROW + k0 + c4;
                b[ni][0] = __float_as_uint(bp[0]);
                b[ni][1] = __float_as_uint(bp[4]);
            }
            #pragma unroll
            for (int mi = 0; mi < 4; mi++)
                #pragma unroll
                for (int ni = 0; ni < NFRAG; ni++)
                    mma_tf32(acc[mi][ni][0], acc[mi][ni][1], acc[mi][ni][2], acc[mi][ni][3],
                             a[mi][0], a[mi][1], a[mi][2], a[mi][3],
                             b[ni][0], b[ni][1]);
        }
        __syncthreads();
    }

    // epilogue
    const int r4 = lane >> 2, c2 = (lane & 3) * 2;
    #pragma unroll
    for (int mi = 0; mi < 4; mi++) {
        const int row0 = bm + warp_m * 64 + mi * 16 + r4;
        #pragma unroll
        for (int ni = 0; ni < NFRAG; ni++) {
            const int col = bn + warp_n * WN + ni * 8 + c2;
            float v0 = acc[mi][ni][0], v1 = acc[mi][ni][1];
            float v2 = acc[mi][ni][2], v3 = acc[mi][ni][3];
            if (EPI == 1) {
                float b0 = bias[col], b1 = bias[col + 1];
                v0 = softplus_f(v0 + b0); v1 = softplus_f(v1 + b1);
                v2 = softplus_f(v2 + b0); v3 = softplus_f(v3 + b1);
            } else if (EPI == 2) {
                const float2 r0 = *reinterpret_cast<const float2*>(res + (size_t)row0 * ldc + col);
                const float2 r1 = *reinterpret_cast<const float2*>(res + (size_t)(row0 + 8) * ldc + col);
                v0 += r0.x; v1 += r0.y; v2 += r1.x; v3 += r1.y;
            }
            *reinterpret_cast<float2*>(C + (size_t)row0 * ldc + col) = make_float2(v0, v1);
            *reinterpret_cast<float2*>(C + (size_t)(row0 + 8) * ldc + col) = make_float2(v2, v3);
        }
    }
}

// ---------------- layernorm (tf32-rounded out) ----------------
__global__ void layernorm_kernel(const float* __restrict__ x,
                                 const float* __restrict__ w,
                                 const float* __restrict__ b,
                                 float* __restrict__ out) {
    int row = blockIdx.x;
    int t = threadIdx.x;
    const float4* xr = reinterpret_cast<const float4*>(x + (size_t)row * DMODEL);
    float4 v = xr[t];
    float s  = v.x + v.y + v.z + v.w;
    float s2 = v.x*v.x + v.y*v.y + v.z*v.z + v.w*v.w;
    #pragma unroll
    for (int o = 16; o; o >>= 1) {
        s  += __shfl_xor_sync(0xffffffffu, s,  o);
        s2 += __shfl_xor_sync(0xffffffffu, s2, o);
    }
    __shared__ float sh[2][8];
    int wid = t >> 5, lid = t & 31;
    if (lid == 0) { sh[0][wid] = s; sh[1][wid] = s2; }
    __syncthreads();
    s = 0.f; s2 = 0.f;
    #pragma unroll
    for (int i = 0; i < 8; i++) { s += sh[0][i]; s2 += sh[1][i]; }
    float mu  = s * (1.f / DMODEL);
    float var = s2 * (1.f / DMODEL) - mu * mu;
    float inv = rsqrtf(var + 1e-5f);
    float4 wv = reinterpret_cast<const float4*>(w)[t];
    float4 bv = reinterpret_cast<const float4*>(b)[t];
    float4 o;
    o.x = rna_tf32((v.x - mu) * inv * wv.x + bv.x);
    o.y = rna_tf32((v.y - mu) * inv * wv.y + bv.y);
    o.z = rna_tf32((v.z - mu) * inv * wv.z + bv.z);
    o.w = rna_tf32((v.w - mu) * inv * wv.w + bv.w);
    reinterpret_cast<float4*>(out + (size_t)row * DMODEL)[t] = o;
}

// ---------------- weight tf32 rounding ----------------
__global__ void cvt_tf32_kernel(const float* __restrict__ src, float* __restrict__ dst, int n4) {
    int i = blockIdx.x * blockDim.x + threadIdx.x;
    if (i < n4) {
        float4 v = reinterpret_cast<const float4*>(src)[i];
        v.x = rna_tf32(v.x); v.y = rna_tf32(v.y);
        v.z = rna_tf32(v.z); v.w = rna_tf32(v.w);
        reinterpret_cast<float4*>(dst)[i] = v;
    }
}

// ---------------- causal depthwise conv (k=4) + silu ----------------
__global__ void conv_silu_kernel(const float* __restrict__ xz,
                                 const float* __restrict__ cw,
                                 const float* __restrict__ cb,
                                 float* __restrict__ xc) {
    int idx = blockIdx.x * blockDim.x + threadIdx.x;
    int d = idx & (DINCH - 1);
    int l = (idx >> 11) & (LSEQ - 1);
    int b = idx >> 21;
    float v = cb[d];
    const float* base = xz + ((size_t)b * LSEQ) * 2 * DINCH + d;
    #pragma unroll
    for (int k = 0; k < DCONV; k++) {
        int li = l - (DCONV - 1) + k;
        if (li >= 0)
            v = fmaf(base[(size_t)li * 2 * DINCH], cw[d * DCONV + k], v);
    }
    v = v / (1.f + __expf(-v));
    xc[idx] = rna_tf32(v);
}

// ---------------- selective scan ----------------
__global__ void scan_kernel(const float* __restrict__ dt,
                            const float* __restrict__ xdbl,
                            const float* __restrict__ xc,
                            const float* __restrict__ xz,
                            const float* __restrict__ A_log,
                            const float* __restrict__ D_skip,
                            float* __restrict__ y) {
    int g = blockIdx.x * blockDim.x + threadIdx.x;
    int n = g & (DSTATE - 1);
    int d = (g >> 4) & (DINCH - 1);
    int b = g >> 15;

    float a   = -__expf(A_log[d * DSTATE + n]);
    float D_d = D_skip[d];
    float h = 0.f;

    const float* dt_p = dt   + (size_t)b * LSEQ * DINCH + d;
    const float* xc_p = xc   + (size_t)b * LSEQ * DINCH + d;
    const float* z_p  = xz   + (size_t)b * LSEQ * 2 * DINCH + DINCH + d;
    const float* B_p  = xdbl + (size_t)b * LSEQ * XDBL_W + DTRANK + n;
    const float* C_p  = B_p + DSTATE;
    float* y_p = y + (size_t)b * LSEQ * DINCH + d;

    float dt_v = __ldg(dt_p);
    float xc_v = __ldg(xc_p);
    float Bv   = __ldg(B_p);
    float Cv   = __ldg(C_p);

    for (int t = 0; t < LSEQ; t++) {
        float dt_c = dt_v, xc_c = xc_v, Bc = Bv, Cc = Cv;
        if (t + 1 < LSEQ) {
            dt_v = __ldg(dt_p + (size_t)(t + 1) * DINCH);
            xc_v = __ldg(xc_p + (size_t)(t + 1) * DINCH);
            Bv   = __ldg(B_p + (size_t)(t + 1) * XDBL_W);
            Cv   = __ldg(C_p + (size_t)(t + 1) * XDBL_W);
        }
        float dA = __expf(dt_c * a);
        h = fmaf(dA, h, dt_c * Bc * xc_c);
        float p = h * Cc;
        p += __shfl_xor_sync(0xffffffffu, p, 8);
        p += __shfl_xor_sync(0xffffffffu, p, 4);
        p += __shfl_xor_sync(0xffffffffu, p, 2);
        p += __shfl_xor_sync(0xffffffffu, p, 1);
        if (n == 0) {
            float zv = __ldg(z_p + (size_t)t * 2 * DINCH);
            float sz = zv / (1.f + __expf(-zv));
            y_p[(size_t)t * DINCH] = rna_tf32((p + xc_c * D_d) * sz);
        }
    }
}

// ---------------- launch ----------------
#define SMEM_GEMM(BN) (2 * (128 + (BN)) * SROW * 4)

extern "C" void kernel_launch(void* const* d_in, const int* in_sizes, int n_in,
                              void* d_out, int out_size) {
    const float* x         = (const float*)d_in[0];
    const float* norm_w    = (const float*)d_in[1];
    const float* norm_b    = (const float*)d_in[2];
    const float* in_proj_w = (const float*)d_in[3];
    const float* conv_w    = (const float*)d_in[4];
    const float* conv_b    = (const float*)d_in[5];
    const float* x_proj_w  = (const float*)d_in[6];
    const float* dt_w      = (const float*)d_in[7];
    const float* dt_b      = (const float*)d_in[8];
    const float* A_log     = (const float*)d_in[9];
    const float* D_skip    = (const float*)d_in[10];
    const float* out_w     = (const float*)d_in[11];
    float* out = (float*)d_out;

    static float *p_h = nullptr, *p_xz, *p_xc, *p_xdbl, *p_dt, *p_y,
                 *p_wa, *p_wb, *p_wc, *p_wd;
    if (!p_h) {
        cudaGetSymbolAddress((void**)&p_h,    g_h);
        cudaGetSymbolAddress((void**)&p_xz,   g_xz);
        cudaGetSymbolAddress((void**)&p_xc,   g_xc);
        cudaGetSymbolAddress((void**)&p_xdbl, g_xdbl);
        cudaGetSymbolAddress((void**)&p_dt,   g_dt);
        cudaGetSymbolAddress((void**)&p_y,    g_y);
        cudaGetSymbolAddress((void**)&p_wa,   g_wa);
        cudaGetSymbolAddress((void**)&p_wb,   g_wb);
        cudaGetSymbolAddress((void**)&p_wc,   g_wc);
        cudaGetSymbolAddress((void**)&p_wd,   g_wd);
        cudaFuncSetAttribute(gemm_mma_kernel<128, 0>,
                             cudaFuncAttributeMaxDynamicSharedMemorySize, SMEM_GEMM(128));
        cudaFuncSetAttribute(gemm_mma_kernel<96, 0>,
                             cudaFuncAttributeMaxDynamicSharedMemorySize, SMEM_GEMM(96));
        cudaFuncSetAttribute(gemm_mma_kernel<128, 1>,
                             cudaFuncAttributeMaxDynamicSharedMemorySize, SMEM_GEMM(128));
        cudaFuncSetAttribute(gemm_mma_kernel<128, 2>,
                             cudaFuncAttributeMaxDynamicSharedMemorySize, SMEM_GEMM(128));
    }

    // 0. weight rounding to tf32
    cvt_tf32_kernel<<<(2 * DINCH * DMODEL / 4 + 255) / 256, 256>>>(in_proj_w, p_wa, 2 * DINCH * DMODEL / 4);
    cvt_tf32_kernel<<<(XDBL_W * DINCH / 4 + 255) / 256, 256>>>(x_proj_w, p_wb, XDBL_W * DINCH / 4);
    cvt_tf32_kernel<<<(DINCH * DTRANK / 4 + 255) / 256, 256>>>(dt_w, p_wc, DINCH * DTRANK / 4);
    cvt_tf32_kernel<<<(DMODEL * DINCH / 4 + 255) / 256, 256>>>(out_w, p_wd, DMODEL * DINCH / 4);

    // 1. layernorm
    layernorm_kernel<<<MROWS, 256>>>(x, norm_w, norm_b, p_h);

    // 2. in_proj: [2048,1024] @ [4096,1024]^T -> xz
    gemm_mma_kernel<128, 0><<<dim3(2 * DINCH / 128, MROWS / 128), 256, SMEM_GEMM(128)>>>(
        p_h, DMODEL, p_wa, nullptr, nullptr, p_xz, 2 * DINCH, DMODEL);

    // 3. conv + silu
    conv_silu_kernel<<<(MROWS * DINCH) / 256, 256>>>(p_xz, conv_w, conv_b, p_xc);

    // 4. x_proj: [2048,2048] @ [96,2048]^T -> x_dbl
    gemm_mma_kernel<96, 0><<<dim3(1, MROWS / 128), 256, SMEM_GEMM(96)>>>(
        p_xc, DINCH, p_wb, nullptr, nullptr, p_xdbl, XDBL_W, DINCH);

    // 5. dt_proj + softplus
    gemm_mma_kernel<128, 1><<<dim3(DINCH / 128, MROWS / 128), 256, SMEM_GEMM(128)>>>(
        p_xdbl, XDBL_W, p_wc, dt_b, nullptr, p_dt, DINCH, DTRANK);

    // 6. selective scan
    scan_kernel<<<(BDIM * DINCH * DSTATE) / 256, 256>>>(p_dt, p_xdbl, p_xc,
                                                        p_xz, A_log, D_skip, p_y);

    // 7. out_proj + residual
    gemm_mma_kernel<128, 2><<<dim3(DMODEL / 128, MROWS / 128), 256, SMEM_GEMM(128)>>>(
        p_y, DINCH, p_wd, nullptr, x, out, DMODEL, DINCH);
}

// round 4
// speedup vs baseline: 3.5861x; 1.8229x over previous
#include <cuda_runtime.h>
#include <cstdint>

#define BDIM   2
#define LSEQ   1024
#define DMODEL 1024
#define DINCH  2048
#define DSTATE 16
#define DCONV  4
#define DTRANK 64
#define MROWS  (BDIM * LSEQ)          // 2048
#define XDBL_W (DTRANK + 2 * DSTATE)  // 96
#define CH     16                     // scan chunks
#define CLEN   (LSEQ / CH)            // 64
#define NSTATES (BDIM * DINCH * DSTATE)  // 65536
#define KSPL   8                      // x_proj split-K

// ---------------- scratch (static device arrays; no allocation) ----------------
__device__ float g_h   [MROWS * DMODEL];
__device__ float g_xz  [MROWS * 2 * DINCH];
__device__ float g_xc  [MROWS * DINCH];
__device__ float g_xdbl[MROWS * XDBL_W];
__device__ float g_xpart[KSPL * MROWS * XDBL_W];
__device__ float g_dt  [MROWS * DINCH];
__device__ float g_y   [MROWS * DINCH];
__device__ float g_P     [CH * NSTATES];
__device__ float g_hend  [CH * NSTATES];
__device__ float g_hstart[CH * NSTATES];
// tf32-rounded weight copies
__device__ float g_wa  [2 * DINCH * DMODEL];
__device__ float g_wb  [XDBL_W * DINCH];
__device__ float g_wc  [DINCH * DTRANK];
__device__ float g_wd  [DMODEL * DINCH];

// ---------------- helpers ----------------
__device__ __forceinline__ float rna_tf32(float x) {
    uint32_t o; asm("cvt.rna.tf32.f32 %0, %1;" : "=r"(o) : "f"(x));
    return __uint_as_float(o);
}
__device__ __forceinline__ void cp_async16(uint32_t s, const void* g) {
    asm volatile("cp.async.ca.shared.global [%0], [%1], 16;" :: "r"(s), "l"(g));
}
__device__ __forceinline__ void cp_commit() {
    asm volatile("cp.async.commit_group;" ::: "memory");
}
__device__ __forceinline__ void cp_wait1() {
    asm volatile("cp.async.wait_group 1;" ::: "memory");
}
__device__ __forceinline__ float softplus_f(float x) {
    return (x > 20.f) ? x : log1pf(__expf(x));
}
__device__ __forceinline__ void mma_tf32(float& c0, float& c1, float& c2, float& c3,
                                         uint32_t a0, uint32_t a1, uint32_t a2, uint32_t a3,
                                         uint32_t b0, uint32_t b1) {
    asm volatile(
        "mma.sync.aligned.m16n8k8.row.col.f32.tf32.tf32.f32 "
        "{%0,%1,%2,%3}, {%4,%5,%6,%7}, {%8,%9}, {%0,%1,%2,%3};"
        : "+f"(c0), "+f"(c1), "+f"(c2), "+f"(c3)
        : "r"(a0), "r"(a1), "r"(a2), "r"(a3), "r"(b0), "r"(b1));
}

// ---------------- tf32 mma.sync GEMM ----------------
// EPI: 0 = none, 1 = softplus(v + bias[n]), 2 = v + res[m*ldc+n]
// KSPLIT > 1: blockIdx.z selects K-slice, C offset by z*MROWS*ldc (partial buffers)
#define SROW 36
template<int BN, int EPI, int KSPLIT>
__global__ void __launch_bounds__(256, 2) gemm_mma_kernel(
    const float* __restrict__ A, int lda,
    const float* __restrict__ W,
    const float* __restrict__ bias,
    const float* __restrict__ res,
    float* __restrict__ C,
    int ldc, int K)
{
    constexpr int WN = BN / 4;
    constexpr int NFRAG = WN / 8;
    constexpr int STAGE = (128 + BN) * SROW;

    extern __shared__ float sm[];
    uint32_t sm_u32;
    asm("{ .reg .u64 t; cvta.to.shared.u64 t, %1; cvt.u32.u64 %0, t; }"
        : "=r"(sm_u32) : "l"(sm));

    const int tid = threadIdx.x;
    const int wid = tid >> 5, lane = tid & 31;
    const int warp_m = wid & 1, warp_n = wid >> 1;
    const int bm = blockIdx.y * 128;
    const int bn = blockIdx.x * BN;

    if (KSPLIT > 1) {
        int kb = blockIdx.z * (K / KSPLIT);
        A += kb; W += kb;
        C += (size_t)blockIdx.z * MROWS * ldc;
        K = K / KSPLIT;
    }
    const int niter = K >> 5;

    const int lrow = tid >> 3;
    const int lch  = (tid & 7) * 4;

    float acc[4][NFRAG][4];
    #pragma unroll
    for (int i = 0; i < 4; i++)
        #pragma unroll
        for (int j = 0; j < NFRAG; j++)
            #pragma unroll
            for (int c = 0; c < 4; c++) acc[i][j][c] = 0.f;

    auto issue_stage = [&](int it, int s) {
        const int k0 = it * 32;
        uint32_t as = sm_u32 + (uint32_t)(s * STAGE) * 4u;
        uint32_t bs = as + 128u * SROW * 4u;
        const float* Ag = A + (size_t)(bm + lrow) * lda + k0 + lch;
        #pragma unroll
        for (int w = 0; w < 4; w++)
            cp_async16(as + ((lrow + 32 * w) * SROW + lch) * 4u,
                       Ag + (size_t)(32 * w) * lda);
        const float* Wg = W + (size_t)(bn + lrow) * lda + k0 + lch;
        #pragma unroll
        for (int w = 0; w < BN / 32; w++)
            cp_async16(bs + ((lrow + 32 * w) * SROW + lch) * 4u,
                       Wg + (size_t)(32 * w) * lda);
    };

    issue_stage(0, 0);
    cp_commit();

    for (int it = 0; it < niter; it++) {
        if (it + 1 < niter) issue_stage(it + 1, (it + 1) & 1);
        cp_commit();
        cp_wait1();
        __syncthreads();

        const float* as = sm + (it & 1) * STAGE;
        const float* bs = as + 128 * SROW;
        const int r4 = lane >> 2, c4 = lane & 3;

        #pragma unroll
        for (int kk = 0; kk < 4; kk++) {
            const int k0 = kk * 8;
            uint32_t a[4][4];
            #pragma unroll
            for (int mi = 0; mi < 4; mi++) {
                const float* ap = as + (warp_m * 64 + mi * 16 + r4) * SROW + k0 + c4;
                a[mi][0] = __float_as_uint(ap[0]);
                a[mi][1] = __float_as_uint(ap[8 * SROW]);
                a[mi][2] = __float_as_uint(ap[4]);
                a[mi][3] = __float_as_uint(ap[8 * SROW + 4]);
            }
            uint32_t b[NFRAG][2];
            #pragma unroll
            for (int ni = 0; ni < NFRAG; ni++) {
                const float* bp = bs + (warp_n * WN + ni * 8 + r4) * SROW + k0 + c4;
                b[ni][0] = __float_as_uint(bp[0]);
                b[ni][1] = __float_as_uint(bp[4]);
            }
            #pragma unroll
            for (int mi = 0; mi < 4; mi++)
                #pragma unroll
                for (int ni = 0; ni < NFRAG; ni++)
                    mma_tf32(acc[mi][ni][0], acc[mi][ni][1], acc[mi][ni][2], acc[mi][ni][3],
                             a[mi][0], a[mi][1], a[mi][2], a[mi][3],
                             b[ni][0], b[ni][1]);
        }
        __syncthreads();
    }

    const int r4 = lane >> 2, c2 = (lane & 3) * 2;
    #pragma unroll
    for (int mi = 0; mi < 4; mi++) {
        const int row0 = bm + warp_m * 64 + mi * 16 + r4;
        #pragma unroll
        for (int ni = 0; ni < NFRAG; ni++) {
            const int col = bn + warp_n * WN + ni * 8 + c2;
            float v0 = acc[mi][ni][0], v1 = acc[mi][ni][1];
            float v2 = acc[mi][ni][2], v3 = acc[mi][ni][3];
            if (EPI == 1) {
                float b0 = bias[col], b1 = bias[col + 1];
                v0 = softplus_f(v0 + b0); v1 = softplus_f(v1 + b1);
                v2 = softplus_f(v2 + b0); v3 = softplus_f(v3 + b1);
            } else if (EPI == 2) {
                const float2 r0 = *reinterpret_cast<const float2*>(res + (size_t)row0 * ldc + col);
                const float2 r1 = *reinterpret_cast<const float2*>(res + (size_t)(row0 + 8) * ldc + col);
                v0 += r0.x; v1 += r0.y; v2 += r1.x; v3 += r1.y;
            }
            *reinterpret_cast<float2*>(C + (size_t)row0 * ldc + col) = make_float2(v0, v1);
            *reinterpret_cast<float2*>(C + (size_t)(row0 + 8) * ldc + col) = make_float2(v2, v3);
        }
    }
}

// ---------------- split-K reduce for x_proj ----------------
__global__ void reduce_xdbl_kernel(float* __restrict__ dst) {
    int i = blockIdx.x * blockDim.x + threadIdx.x;
    if (i < MROWS * XDBL_W) {
        float s = 0.f;
        #pragma unroll
        for (int p = 0; p < KSPL; p++) s += g_xpart[p * (MROWS * XDBL_W) + i];
        dst[i] = s;
    }
}

// ---------------- layernorm ----------------
__global__ void layernorm_kernel(const float* __restrict__ x,
                                 const float* __restrict__ w,
                                 const float* __restrict__ b,
                                 float* __restrict__ out) {
    int row = blockIdx.x;
    int t = threadIdx.x;
    const float4* xr = reinterpret_cast<const float4*>(x + (size_t)row * DMODEL);
    float4 v = xr[t];
    float s  = v.x + v.y + v.z + v.w;
    float s2 = v.x*v.x + v.y*v.y + v.z*v.z + v.w*v.w;
    #pragma unroll
    for (int o = 16; o; o >>= 1) {
        s  += __shfl_xor_sync(0xffffffffu, s,  o);
        s2 += __shfl_xor_sync(0xffffffffu, s2, o);
    }
    __shared__ float sh[2][8];
    int wid = t >> 5, lid = t & 31;
    if (lid == 0) { sh[0][wid] = s; sh[1][wid] = s2; }
    __syncthreads();
    s = 0.f; s2 = 0.f;
    #pragma unroll
    for (int i = 0; i < 8; i++) { s += sh[0][i]; s2 += sh[1][i]; }
    float mu  = s * (1.f / DMODEL);
    float var = s2 * (1.f / DMODEL) - mu * mu;
    float inv = rsqrtf(var + 1e-5f);
    float4 wv = reinterpret_cast<const float4*>(w)[t];
    float4 bv = reinterpret_cast<const float4*>(b)[t];
    float4 o;
    o.x = rna_tf32((v.x - mu) * inv * wv.x + bv.x);
    o.y = rna_tf32((v.y - mu) * inv * wv.y + bv.y);
    o.z = rna_tf32((v.z - mu) * inv * wv.z + bv.z);
    o.w = rna_tf32((v.w - mu) * inv * wv.w + bv.w);
    reinterpret_cast<float4*>(out + (size_t)row * DMODEL)[t] = o;
}

// ---------------- weight tf32 rounding ----------------
__global__ void cvt_tf32_kernel(const float* __restrict__ src, float* __restrict__ dst, int n4) {
    int i = blockIdx.x * blockDim.x + threadIdx.x;
    if (i < n4) {
        float4 v = reinterpret_cast<const float4*>(src)[i];
        v.x = rna_tf32(v.x); v.y = rna_tf32(v.y);
        v.z = rna_tf32(v.z); v.w = rna_tf32(v.w);
        reinterpret_cast<float4*>(dst)[i] = v;
    }
}

// ---------------- causal depthwise conv (k=4) + silu ----------------
__global__ void conv_silu_kernel(const float* __restrict__ xz,
                                 const float* __restrict__ cw,
                                 const float* __restrict__ cb,
                                 float* __restrict__ xc) {
    int idx = blockIdx.x * blockDim.x + threadIdx.x;
    int d = idx & (DINCH - 1);
    int l = (idx >> 11) & (LSEQ - 1);
    int b = idx >> 21;
    float v = cb[d];
    const float* base = xz + ((size_t)b * LSEQ) * 2 * DINCH + d;
    #pragma unroll
    for (int k = 0; k < DCONV; k++) {
        int li = l - (DCONV - 1) + k;
        if (li >= 0)
            v = fmaf(base[(size_t)li * 2 * DINCH], cw[d * DCONV + k], v);
    }
    v = v / (1.f + __expf(-v));
    xc[idx] = rna_tf32(v);
}

// ---------------- chunked scan: pass A (local scans) ----------------
__global__ void scan_passA(const float* __restrict__ dt,
                           const float* __restrict__ xdbl,
                           const float* __restrict__ xc,
                           const float* __restrict__ A_log) {
    int i = blockIdx.x * blockDim.x + threadIdx.x;   // 0..65535
    int ch = blockIdx.y;
    int n = i & (DSTATE - 1);
    int d = (i >> 4) & (DINCH - 1);
    int b = i >> 15;
    int t0 = ch * CLEN;

    float a = -__expf(A_log[d * DSTATE + n]);
    const float* dt_p = dt   + ((size_t)b * LSEQ + t0) * DINCH + d;
    const float* xc_p = xc   + ((size_t)b * LSEQ + t0) * DINCH + d;
    const float* B_p  = xdbl + ((size_t)b * LSEQ + t0) * XDBL_W + DTRANK + n;

    float h = 0.f, P = 1.f;
    float dt_v = __ldg(dt_p), xc_v = __ldg(xc_p), Bv = __ldg(B_p);
    for (int t = 0; t < CLEN; t++) {
        float dt_c = dt_v, xc_c = xc_v, Bc = Bv;
        if (t + 1 < CLEN) {
            dt_v = __ldg(dt_p + (size_t)(t + 1) * DINCH);
            xc_v = __ldg(xc_p + (size_t)(t + 1) * DINCH);
            Bv   = __ldg(B_p + (size_t)(t + 1) * XDBL_W);
        }
        float dA = __expf(dt_c * a);
        h = fmaf(dA, h, dt_c * Bc * xc_c);
        P *= dA;
    }
    g_P[ch * NSTATES + i] = P;
    g_hend[ch * NSTATES + i] = h;
}

// ---------------- chunked scan: pass B (chunk stitch) ----------------
__global__ void scan_passB() {
    int i = blockIdx.x * blockDim.x + threadIdx.x;   // 0..65535
    float h = 0.f;
    #pragma unroll
    for (int ch = 0; ch < CH; ch++) {
        g_hstart[ch * NSTATES + i] = h;
        h = fmaf(g_P[ch * NSTATES + i], h, g_hend[ch * NSTATES + i]);
    }
}

// ---------------- chunked scan: pass C (emit y) ----------------
__global__ void scan_passC(const float* __restrict__ dt,
                           const float* __restrict__ xdbl,
                           const float* __restrict__ xc,
                           const float* __restrict__ xz,
                           const float* __restrict__ A_log,
                           const float* __restrict__ D_skip,
                           float* __restrict__ y) {
    int i = blockIdx.x * blockDim.x + threadIdx.x;
    int ch = blockIdx.y;
    int n = i & (DSTATE - 1);
    int d = (i >> 4) & (DINCH - 1);
    int b = i >> 15;
    int t0 = ch * CLEN;

    float a   = -__expf(A_log[d * DSTATE + n]);
    float D_d = D_skip[d];
    float h = g_hstart[ch * NSTATES + i];

    const float* dt_p = dt   + ((size_t)b * LSEQ + t0) * DINCH + d;
    const float* xc_p = xc   + ((size_t)b * LSEQ + t0) * DINCH + d;
    const float* z_p  = xz   + ((size_t)b * LSEQ + t0) * 2 * DINCH + DINCH + d;
    const float* B_p  = xdbl + ((size_t)b * LSEQ + t0) * XDBL_W + DTRANK + n;
    const float* C_p  = B_p + DSTATE;
    float* y_p = y + ((size_t)b * LSEQ + t0) * DINCH + d;

    float dt_v = __ldg(dt_p), xc_v = __ldg(xc_p);
    float Bv = __ldg(B_p), Cv = __ldg(C_p);

    for (int t = 0; t < CLEN; t++) {
        float dt_c = dt_v, xc_c = xc_v, Bc = Bv, Cc = Cv;
        if (t + 1 < CLEN) {
            dt_v = __ldg(dt_p + (size_t)(t + 1) * DINCH);
            xc_v = __ldg(xc_p + (size_t)(t + 1) * DINCH);
            Bv   = __ldg(B_p + (size_t)(t + 1) * XDBL_W);
            Cv   = __ldg(C_p + (size_t)(t + 1) * XDBL_W);
        }
        float dA = __expf(dt_c * a);
        h = fmaf(dA, h, dt_c * Bc * xc_c);
        float p = h * Cc;
        p += __shfl_xor_sync(0xffffffffu, p, 8);
        p += __shfl_xor_sync(0xffffffffu, p, 4);
        p += __shfl_xor_sync(0xffffffffu, p, 2);
        p += __shfl_xor_sync(0xffffffffu, p, 1);
        if (n == 0) {
            float zv = __ldg(z_p + (size_t)t * 2 * DINCH);
            float sz = zv / (1.f + __expf(-zv));
            y_p[(size_t)t * DINCH] = rna_tf32((p + xc_c * D_d) * sz);
        }
    }
}

// ---------------- launch ----------------
#define SMEM_GEMM(BN) (2 * (128 + (BN)) * SROW * 4)

extern "C" void kernel_launch(void* const* d_in, const int* in_sizes, int n_in,
                              void* d_out, int out_size) {
    const float* x         = (const float*)d_in[0];
    const float* norm_w    = (const float*)d_in[1];
    const float* norm_b    = (const float*)d_in[2];
    const float* in_proj_w = (const float*)d_in[3];
    const float* conv_w    = (const float*)d_in[4];
    const float* conv_b    = (const float*)d_in[5];
    const float* x_proj_w  = (const float*)d_in[6];
    const float* dt_w      = (const float*)d_in[7];
    const float* dt_b      = (const float*)d_in[8];
    const float* A_log     = (const float*)d_in[9];
    const float* D_skip    = (const float*)d_in[10];
    const float* out_w     = (const float*)d_in[11];
    float* out = (float*)d_out;

    static float *p_h = nullptr, *p_xz, *p_xc, *p_xdbl, *p_xpart, *p_dt, *p_y,
                 *p_wa, *p_wb, *p_wc, *p_wd;
    if (!p_h) {
        cudaGetSymbolAddress((void**)&p_h,     g_h);
        cudaGetSymbolAddress((void**)&p_xz,    g_xz);
        cudaGetSymbolAddress((void**)&p_xc,    g_xc);
        cudaGetSymbolAddress((void**)&p_xdbl,  g_xdbl);
        cudaGetSymbolAddress((void**)&p_xpart, g_xpart);
        cudaGetSymbolAddress((void**)&p_dt,    g_dt);
        cudaGetSymbolAddress((void**)&p_y,     g_y);
        cudaGetSymbolAddress((void**)&p_wa,    g_wa);
        cudaGetSymbolAddress((void**)&p_wb,    g_wb);
        cudaGetSymbolAddress((void**)&p_wc,    g_wc);
        cudaGetSymbolAddress((void**)&p_wd,    g_wd);
        cudaFuncSetAttribute(gemm_mma_kernel<128, 0, 1>,
                             cudaFuncAttributeMaxDynamicSharedMemorySize, SMEM_GEMM(128));
        cudaFuncSetAttribute(gemm_mma_kernel<96, 0, KSPL>,
                             cudaFuncAttributeMaxDynamicSharedMemorySize, SMEM_GEMM(96));
        cudaFuncSetAttribute(gemm_mma_kernel<128, 1, 1>,
                             cudaFuncAttributeMaxDynamicSharedMemorySize, SMEM_GEMM(128));
        cudaFuncSetAttribute(gemm_mma_kernel<128, 2, 1>,
                             cudaFuncAttributeMaxDynamicSharedMemorySize, SMEM_GEMM(128));
    }

    // 0. weight rounding to tf32
    cvt_tf32_kernel<<<(2 * DINCH * DMODEL / 4 + 255) / 256, 256>>>(in_proj_w, p_wa, 2 * DINCH * DMODEL / 4);
    cvt_tf32_kernel<<<(XDBL_W * DINCH / 4 + 255) / 256, 256>>>(x_proj_w, p_wb, XDBL_W * DINCH / 4);
    cvt_tf32_kernel<<<(DINCH * DTRANK / 4 + 255) / 256, 256>>>(dt_w, p_wc, DINCH * DTRANK / 4);
    cvt_tf32_kernel<<<(DMODEL * DINCH / 4 + 255) / 256, 256>>>(out_w, p_wd, DMODEL * DINCH / 4);

    // 1. layernorm
    layernorm_kernel<<<MROWS, 256>>>(x, norm_w, norm_b, p_h);

    // 2. in_proj
    gemm_mma_kernel<128, 0, 1><<<dim3(2 * DINCH / 128, MROWS / 128), 256, SMEM_GEMM(128)>>>(
        p_h, DMODEL, p_wa, nullptr, nullptr, p_xz, 2 * DINCH, DMODEL);

    // 3. conv + silu
    conv_silu_kernel<<<(MROWS * DINCH) / 256, 256>>>(p_xz, conv_w, conv_b, p_xc);

    // 4. x_proj (split-K=8, deterministic partials + reduce)
    gemm_mma_kernel<96, 0, KSPL><<<dim3(1, MROWS / 128, KSPL), 256, SMEM_GEMM(96)>>>(
        p_xc, DINCH, p_wb, nullptr, nullptr, p_xpart, XDBL_W, DINCH);
    reduce_xdbl_kernel<<<(MROWS * XDBL_W + 255) / 256, 256>>>(p_xdbl);

    // 5. dt_proj + softplus
    gemm_mma_kernel<128, 1, 1><<<dim3(DINCH / 128, MROWS / 128), 256, SMEM_GEMM(128)>>>(
        p_xdbl, XDBL_W, p_wc, dt_b, nullptr, p_dt, DINCH, DTRANK);

    // 6. chunked selective scan (3 passes)
    scan_passA<<<dim3(NSTATES / 256, CH), 256>>>(p_dt, p_xdbl, p_xc, A_log);
    scan_passB<<<NSTATES / 256, 256>>>();
    scan_passC<<<dim3(NSTATES / 256, CH), 256>>>(p_dt, p_xdbl, p_xc, p_xz,
                                                 A_log, D_skip, p_y);

    // 7. out_proj + residual
    gemm_mma_kernel<128, 2, 1><<<dim3(DMODEL / 128, MROWS / 128), 256, SMEM_GEMM(128)>>>(
        p_y, DINCH, p_wd, nullptr, x, out, DMODEL, DINCH);
}

// round 5
// speedup vs baseline: 5.0812x; 1.4169x over previous
#include <cuda_runtime.h>
#include <cstdint>

#define BDIM   2
#define LSEQ   1024
#define DMODEL 1024
#define DINCH  2048
#define DSTATE 16
#define DCONV  4
#define DTRANK 64
#define MROWS  (BDIM * LSEQ)          // 2048
#define XDBL_W (DTRANK + 2 * DSTATE)  // 96
#define CH     16                     // scan chunks
#define CLEN   (LSEQ / CH)            // 64
#define NBD    (BDIM * DINCH)         // 4096 (b,d) pairs
#define PLANE  (CH * NBD)             // 65536 per n-plane
#define KSPL   8                      // x_proj split-K

// ---------------- scratch (static device arrays; no allocation) ----------------
__device__ float g_h   [MROWS * DMODEL];
__device__ float g_xz  [MROWS * 2 * DINCH];
__device__ float g_xc  [MROWS * DINCH];
__device__ float g_xdbl[MROWS * XDBL_W];
__device__ float g_xpart[KSPL * MROWS * XDBL_W];
__device__ float g_dt  [MROWS * DINCH];
__device__ float g_y   [MROWS * DINCH];
__device__ float g_P     [DSTATE * PLANE];   // planar by n
__device__ float g_hend  [DSTATE * PLANE];
__device__ float g_hstart[DSTATE * PLANE];

// ---------------- helpers ----------------
__device__ __forceinline__ void cp_async16(uint32_t s, const void* g) {
    asm volatile("cp.async.ca.shared.global [%0], [%1], 16;" :: "r"(s), "l"(g));
}
__device__ __forceinline__ void cp_commit() {
    asm volatile("cp.async.commit_group;" ::: "memory");
}
__device__ __forceinline__ void cp_wait1() {
    asm volatile("cp.async.wait_group 1;" ::: "memory");
}
__device__ __forceinline__ float softplus_f(float x) {
    return (x > 20.f) ? x : log1pf(__expf(x));
}
// fp32 bits -> tf32 RNA rounding (add half-ulp of tf32; HW truncates low 13 bits)
__device__ __forceinline__ uint32_t tf32_rna_bits(float x) {
    return __float_as_uint(x) + 0x1000u;
}
__device__ __forceinline__ void mma_tf32(float& c0, float& c1, float& c2, float& c3,
                                         uint32_t a0, uint32_t a1, uint32_t a2, uint32_t a3,
                                         uint32_t b0, uint32_t b1) {
    asm volatile(
        "mma.sync.aligned.m16n8k8.row.col.f32.tf32.tf32.f32 "
        "{%0,%1,%2,%3}, {%4,%5,%6,%7}, {%8,%9}, {%0,%1,%2,%3};"
        : "+f"(c0), "+f"(c1), "+f"(c2), "+f"(c3)
        : "r"(a0), "r"(a1), "r"(a2), "r"(a3), "r"(b0), "r"(b1));
}

// ---------------- tf32 mma.sync GEMM: C = epi(A[M,K] @ W[N,K]^T) ----------------
// EPI: 0 = none, 1 = softplus(v + bias[n]), 2 = v + res[m*ldc+n]
// KSPLIT > 1: blockIdx.z selects K-slice; C offset by z*MROWS*ldc (partials)
#define SROW 36
template<int BN, int EPI, int KSPLIT>
__global__ void __launch_bounds__(256, 2) gemm_mma_kernel(
    const float* __restrict__ A, int lda,
    const float* __restrict__ W, int ldw,
    const float* __restrict__ bias,
    const float* __restrict__ res,
    float* __restrict__ C,
    int ldc, int K)
{
    constexpr int WN = BN / 4;
    constexpr int NFRAG = WN / 8;
    constexpr int STAGE = (128 + BN) * SROW;

    extern __shared__ float sm[];
    uint32_t sm_u32;
    asm("{ .reg .u64 t; cvta.to.shared.u64 t, %1; cvt.u32.u64 %0, t; }"
        : "=r"(sm_u32) : "l"(sm));

    const int tid = threadIdx.x;
    const int wid = tid >> 5, lane = tid & 31;
    const int warp_m = wid & 1, warp_n = wid >> 1;
    const int bm = blockIdx.y * 128;
    const int bn = blockIdx.x * BN;

    if (KSPLIT > 1) {
        int kb = blockIdx.z * (K / KSPLIT);
        A += kb; W += kb;
        C += (size_t)blockIdx.z * MROWS * ldc;
        K = K / KSPLIT;
    }
    const int niter = K >> 5;

    const int lrow = tid >> 3;
    const int lch  = (tid & 7) * 4;

    float acc[4][NFRAG][4];
    #pragma unroll
    for (int i = 0; i < 4; i++)
        #pragma unroll
        for (int j = 0; j < NFRAG; j++)
            #pragma unroll
            for (int c = 0; c < 4; c++) acc[i][j][c] = 0.f;

    auto issue_stage = [&](int it, int s) {
        const int k0 = it * 32;
        uint32_t as = sm_u32 + (uint32_t)(s * STAGE) * 4u;
        uint32_t bs = as + 128u * SROW * 4u;
        const float* Ag = A + (size_t)(bm + lrow) * lda + k0 + lch;
        #pragma unroll
        for (int w = 0; w < 4; w++)
            cp_async16(as + ((lrow + 32 * w) * SROW + lch) * 4u,
                       Ag + (size_t)(32 * w) * lda);
        const float* Wg = W + (size_t)(bn + lrow) * ldw + k0 + lch;
        #pragma unroll
        for (int w = 0; w < BN / 32; w++)
            cp_async16(bs + ((lrow + 32 * w) * SROW + lch) * 4u,
                       Wg + (size_t)(32 * w) * ldw);
    };

    issue_stage(0, 0);
    cp_commit();

    for (int it = 0; it < niter; it++) {
        if (it + 1 < niter) issue_stage(it + 1, (it + 1) & 1);
        cp_commit();
        cp_wait1();
        __syncthreads();

        const float* as = sm + (it & 1) * STAGE;
        const float* bs = as + 128 * SROW;
        const int r4 = lane >> 2, c4 = lane & 3;

        #pragma unroll
        for (int kk = 0; kk < 4; kk++) {
            const int k0 = kk * 8;
            uint32_t a[4][4];
            #pragma unroll
            for (int mi = 0; mi < 4; mi++) {
                const float* ap = as + (warp_m * 64 + mi * 16 + r4) * SROW + k0 + c4;
                a[mi][0] = tf32_rna_bits(ap[0]);
                a[mi][1] = tf32_rna_bits(ap[8 * SROW]);
                a[mi][2] = tf32_rna_bits(ap[4]);
                a[mi][3] = tf32_rna_bits(ap[8 * SROW + 4]);
            }
            uint32_t b[NFRAG][2];
            #pragma unroll
            for (int ni = 0; ni < NFRAG; ni++) {
                const float* bp = bs + (warp_n * WN + ni * 8 + r4) * SROW + k0 + c4;
                b[ni][0] = tf32_rna_bits(bp[0]);
                b[ni][1] = tf32_rna_bits(bp[4]);
            }
            #pragma unroll
            for (int mi = 0; mi < 4; mi++)
                #pragma unroll
                for (int ni = 0; ni < NFRAG; ni++)
                    mma_tf32(acc[mi][ni][0], acc[mi][ni][1], acc[mi][ni][2], acc[mi][ni][3],
                             a[mi][0], a[mi][1], a[mi][2], a[mi][3],
                             b[ni][0], b[ni][1]);
        }
        __syncthreads();
    }

    const int r4 = lane >> 2, c2 = (lane & 3) * 2;
    #pragma unroll
    for (int mi = 0; mi < 4; mi++) {
        const int row0 = bm + warp_m * 64 + mi * 16 + r4;
        #pragma unroll
        for (int ni = 0; ni < NFRAG; ni++) {
            const int col = bn + warp_n * WN + ni * 8 + c2;
            float v0 = acc[mi][ni][0], v1 = acc[mi][ni][1];
            float v2 = acc[mi][ni][2], v3 = acc[mi][ni][3];
            if (EPI == 1) {
                float b0 = bias[col], b1 = bias[col + 1];
                v0 = softplus_f(v0 + b0); v1 = softplus_f(v1 + b1);
                v2 = softplus_f(v2 + b0); v3 = softplus_f(v3 + b1);
            } else if (EPI == 2) {
                const float2 r0 = *reinterpret_cast<const float2*>(res + (size_t)row0 * ldc + col);
                const float2 r1 = *reinterpret_cast<const float2*>(res + (size_t)(row0 + 8) * ldc + col);
                v0 += r0.x; v1 += r0.y; v2 += r1.x; v3 += r1.y;
            }
            *reinterpret_cast<float2*>(C + (size_t)row0 * ldc + col) = make_float2(v0, v1);
            *reinterpret_cast<float2*>(C + (size_t)(row0 + 8) * ldc + col) = make_float2(v2, v3);
        }
    }
}

// ---------------- split-K reduce for x_proj ----------------
__global__ void reduce_xdbl_kernel(float* __restrict__ dst) {
    int i = blockIdx.x * blockDim.x + threadIdx.x;
    if (i < MROWS * XDBL_W) {
        float s = 0.f;
        #pragma unroll
        for (int p = 0; p < KSPL; p++) s += g_xpart[p * (MROWS * XDBL_W) + i];
        dst[i] = s;
    }
}

// ---------------- layernorm ----------------
__global__ void layernorm_kernel(const float* __restrict__ x,
                                 const float* __restrict__ w,
                                 const float* __restrict__ b,
                                 float* __restrict__ out) {
    int row = blockIdx.x;
    int t = threadIdx.x;
    const float4* xr = reinterpret_cast<const float4*>(x + (size_t)row * DMODEL);
    float4 v = xr[t];
    float s  = v.x + v.y + v.z + v.w;
    float s2 = v.x*v.x + v.y*v.y + v.z*v.z + v.w*v.w;
    #pragma unroll
    for (int o = 16; o; o >>= 1) {
        s  += __shfl_xor_sync(0xffffffffu, s,  o);
        s2 += __shfl_xor_sync(0xffffffffu, s2, o);
    }
    __shared__ float sh[2][8];
    int wid = t >> 5, lid = t & 31;
    if (lid == 0) { sh[0][wid] = s; sh[1][wid] = s2; }
    __syncthreads();
    s = 0.f; s2 = 0.f;
    #pragma unroll
    for (int i = 0; i < 8; i++) { s += sh[0][i]; s2 += sh[1][i]; }
    float mu  = s * (1.f / DMODEL);
    float var = s2 * (1.f / DMODEL) - mu * mu;
    float inv = rsqrtf(var + 1e-5f);
    float4 wv = reinterpret_cast<const float4*>(w)[t];
    float4 bv = reinterpret_cast<const float4*>(b)[t];
    float4 o;
    o.x = (v.x - mu) * inv * wv.x + bv.x;
    o.y = (v.y - mu) * inv * wv.y + bv.y;
    o.z = (v.z - mu) * inv * wv.z + bv.z;
    o.w = (v.w - mu) * inv * wv.w + bv.w;
    reinterpret_cast<float4*>(out + (size_t)row * DMODEL)[t] = o;
}

// ---------------- causal depthwise conv (k=4) + silu ----------------
__global__ void conv_silu_kernel(const float* __restrict__ xz,
                                 const float* __restrict__ cw,
                                 const float* __restrict__ cb,
                                 float* __restrict__ xc) {
    int idx = blockIdx.x * blockDim.x + threadIdx.x;
    int d = idx & (DINCH - 1);
    int l = (idx >> 11) & (LSEQ - 1);
    int b = idx >> 21;
    float v = cb[d];
    const float* base = xz + ((size_t)b * LSEQ) * 2 * DINCH + d;
    #pragma unroll
    for (int k = 0; k < DCONV; k++) {
        int li = l - (DCONV - 1) + k;
        if (li >= 0)
            v = fmaf(base[(size_t)li * 2 * DINCH], cw[d * DCONV + k], v);
    }
    v = v / (1.f + __expf(-v));
    xc[idx] = v;
}

// ---------------- chunked scan, 16 n-states per thread ----------------
// thread -> (b, d, ch); block 256 threads over d; grid (DINCH/256, BDIM, CH)
__global__ void __launch_bounds__(256) scan_passA(
    const float* __restrict__ dt,
    const float* __restrict__ xdbl,
    const float* __restrict__ xc,
    const float* __restrict__ A_log)
{
    const int d  = blockIdx.x * 256 + threadIdx.x;
    const int b  = blockIdx.y;
    const int ch = blockIdx.z;
    const int t0 = ch * CLEN;

    float a[DSTATE];
    {
        const float4* ar = reinterpret_cast<const float4*>(A_log + d * DSTATE);
        #pragma unroll
        for (int q = 0; q < 4; q++) {
            float4 v = ar[q];
            a[q*4+0] = -__expf(v.x); a[q*4+1] = -__expf(v.y);
            a[q*4+2] = -__expf(v.z); a[q*4+3] = -__expf(v.w);
        }
    }
    float h[DSTATE], P[DSTATE];
    #pragma unroll
    for (int n = 0; n < DSTATE; n++) { h[n] = 0.f; P[n] = 1.f; }

    const float* dt_p = dt + ((size_t)b * LSEQ + t0) * DINCH + d;
    const float* xc_p = xc + ((size_t)b * LSEQ + t0) * DINCH + d;
    const float* Bb   = xdbl + ((size_t)b * LSEQ + t0) * XDBL_W + DTRANK;

    for (int t = 0; t < CLEN; t++) {
        float dtc = __ldg(dt_p + (size_t)t * DINCH);
        float xcc = __ldg(xc_p + (size_t)t * DINCH);
        float Bv[DSTATE];
        #pragma unroll
        for (int q = 0; q < 4; q++) {
            float4 v = *reinterpret_cast<const float4*>(Bb + (size_t)t * XDBL_W + q * 4);
            Bv[q*4+0] = v.x; Bv[q*4+1] = v.y; Bv[q*4+2] = v.z; Bv[q*4+3] = v.w;
        }
        float dtxc = dtc * xcc;
        #pragma unroll
        for (int n = 0; n < DSTATE; n++) {
            float dA = __expf(dtc * a[n]);
            h[n] = fmaf(dA, h[n], dtxc * Bv[n]);
            P[n] *= dA;
        }
    }
    const int s = (ch * BDIM + b) * DINCH + d;
    #pragma unroll
    for (int n = 0; n < DSTATE; n++) {
        g_hend[n * PLANE + s] = h[n];
        g_P[n * PLANE + s]    = P[n];
    }
}

__global__ void scan_passB() {
    int i = blockIdx.x * blockDim.x + threadIdx.x;   // 0..65535
    int d = i & (DINCH - 1);
    int b = (i >> 11) & (BDIM - 1);
    int n = i >> 12;
    float h = 0.f;
    #pragma unroll
    for (int ch = 0; ch < CH; ch++) {
        int s = (ch * BDIM + b) * DINCH + d;
        g_hstart[n * PLANE + s] = h;
        h = fmaf(g_P[n * PLANE + s], h, g_hend[n * PLANE + s]);
    }
}

__global__ void __launch_bounds__(256) scan_passC(
    const float* __restrict__ dt,
    const float* __restrict__ xdbl,
    const float* __restrict__ xc,
    const float* __restrict__ xz,
    const float* __restrict__ A_log,
    const float* __restrict__ D_skip,
    float* __restrict__ y)
{
    const int d  = blockIdx.x * 256 + threadIdx.x;
    const int b  = blockIdx.y;
    const int ch = blockIdx.z;
    const int t0 = ch * CLEN;

    float a[DSTATE];
    {
        const float4* ar = reinterpret_cast<const float4*>(A_log + d * DSTATE);
        #pragma unroll
        for (int q = 0; q < 4; q++) {
            float4 v = ar[q];
            a[q*4+0] = -__expf(v.x); a[q*4+1] = -__expf(v.y);
            a[q*4+2] = -__expf(v.z); a[q*4+3] = -__expf(v.w);
        }
    }
    float h[DSTATE];
    {
        const int s = (ch * BDIM + b) * DINCH + d;
        #pragma unroll
        for (int n = 0; n < DSTATE; n++) h[n] = g_hstart[n * PLANE + s];
    }
    const float D_d = __ldg(D_skip + d);

    const float* dt_p = dt + ((size_t)b * LSEQ + t0) * DINCH + d;
    const float* xc_p = xc + ((size_t)b * LSEQ + t0) * DINCH + d;
    const float* z_p  = xz + ((size_t)b * LSEQ + t0) * 2 * DINCH + DINCH + d;
    const float* Bb   = xdbl + ((size_t)b * LSEQ + t0) * XDBL_W + DTRANK;
    float* y_p = y + ((size_t)b * LSEQ + t0) * DINCH + d;

    for (int t = 0; t < CLEN; t++) {
        float dtc = __ldg(dt_p + (size_t)t * DINCH);
        float xcc = __ldg(xc_p + (size_t)t * DINCH);
        float Bv[DSTATE], Cv[DSTATE];
        #pragma unroll
        for (int q = 0; q < 4; q++) {
            float4 v = *reinterpret_cast<const float4*>(Bb + (size_t)t * XDBL_W + q * 4);
            Bv[q*4+0] = v.x; Bv[q*4+1] = v.y; Bv[q*4+2] = v.z; Bv[q*4+3] = v.w;
            float4 c = *reinterpret_cast<const float4*>(Bb + (size_t)t * XDBL_W + DSTATE + q * 4);
            Cv[q*4+0] = c.x; Cv[q*4+1] = c.y; Cv[q*4+2] = c.z; Cv[q*4+3] = c.w;
        }
        float dtxc = dtc * xcc;
        float p = 0.f;
        #pragma unroll
        for (int n = 0; n < DSTATE; n++) {
            float dA = __expf(dtc * a[n]);
            h[n] = fmaf(dA, h[n], dtxc * Bv[n]);
            p = fmaf(h[n], Cv[n], p);
        }
        float zv = __ldg(z_p + (size_t)t * 2 * DINCH);
        float sz = zv / (1.f + __expf(-zv));
        y_p[(size_t)t * DINCH] = (p + xcc * D_d) * sz;
    }
}

// ---------------- launch ----------------
#define SMEM_GEMM(BN) (2 * (128 + (BN)) * SROW * 4)

extern "C" void kernel_launch(void* const* d_in, const int* in_sizes, int n_in,
                              void* d_out, int out_size) {
    const float* x         = (const float*)d_in[0];
    const float* norm_w    = (const float*)d_in[1];
    const float* norm_b    = (const float*)d_in[2];
    const float* in_proj_w = (const float*)d_in[3];
    const float* conv_w    = (const float*)d_in[4];
    const float* conv_b    = (const float*)d_in[5];
    const float* x_proj_w  = (const float*)d_in[6];
    const float* dt_w      = (const float*)d_in[7];
    const float* dt_b      = (const float*)d_in[8];
    const float* A_log     = (const float*)d_in[9];
    const float* D_skip    = (const float*)d_in[10];
    const float* out_w     = (const float*)d_in[11];
    float* out = (float*)d_out;

    static float *p_h = nullptr, *p_xz, *p_xc, *p_xdbl, *p_xpart, *p_dt, *p_y;
    if (!p_h) {
        cudaGetSymbolAddress((void**)&p_h,     g_h);
        cudaGetSymbolAddress((void**)&p_xz,    g_xz);
        cudaGetSymbolAddress((void**)&p_xc,    g_xc);
        cudaGetSymbolAddress((void**)&p_xdbl,  g_xdbl);
        cudaGetSymbolAddress((void**)&p_xpart, g_xpart);
        cudaGetSymbolAddress((void**)&p_dt,    g_dt);
        cudaGetSymbolAddress((void**)&p_y,     g_y);
        cudaFuncSetAttribute(gemm_mma_kernel<128, 0, 1>,
                             cudaFuncAttributeMaxDynamicSharedMemorySize, SMEM_GEMM(128));
        cudaFuncSetAttribute(gemm_mma_kernel<96, 0, KSPL>,
                             cudaFuncAttributeMaxDynamicSharedMemorySize, SMEM_GEMM(96));
        cudaFuncSetAttribute(gemm_mma_kernel<128, 1, 1>,
                             cudaFuncAttributeMaxDynamicSharedMemorySize, SMEM_GEMM(128));
        cudaFuncSetAttribute(gemm_mma_kernel<128, 2, 1>,
                             cudaFuncAttributeMaxDynamicSharedMemorySize, SMEM_GEMM(128));
    }

    // 1. layernorm
    layernorm_kernel<<<MROWS, 256>>>(x, norm_w, norm_b, p_h);

    // 2. in_proj: [2048,1024] @ [4096,1024]^T -> xz
    gemm_mma_kernel<128, 0, 1><<<dim3(2 * DINCH / 128, MROWS / 128), 256, SMEM_GEMM(128)>>>(
        p_h, DMODEL, in_proj_w, DMODEL, nullptr, nullptr, p_xz, 2 * DINCH, DMODEL);

    // 3. conv + silu
    conv_silu_kernel<<<(MROWS * DINCH) / 256, 256>>>(p_xz, conv_w, conv_b, p_xc);

    // 4. x_proj (split-K=8 partials + reduce)
    gemm_mma_kernel<96, 0, KSPL><<<dim3(1, MROWS / 128, KSPL), 256, SMEM_GEMM(96)>>>(
        p_xc, DINCH, x_proj_w, DINCH, nullptr, nullptr, p_xpart, XDBL_W, DINCH);
    reduce_xdbl_kernel<<<(MROWS * XDBL_W + 255) / 256, 256>>>(p_xdbl);

    // 5. dt_proj + softplus
    gemm_mma_kernel<128, 1, 1><<<dim3(DINCH / 128, MROWS / 128), 256, SMEM_GEMM(128)>>>(
        p_xdbl, XDBL_W, dt_w, DTRANK, dt_b, nullptr, p_dt, DINCH, DTRANK);

    // 6. chunked selective scan (3 passes, 16 states per thread)
    scan_passA<<<dim3(DINCH / 256, BDIM, CH), 256>>>(p_dt, p_xdbl, p_xc, A_log);
    scan_passB<<<(DSTATE * NBD) / 256, 256>>>();
    scan_passC<<<dim3(DINCH / 256, BDIM, CH), 256>>>(p_dt, p_xdbl, p_xc, p_xz,
                                                     A_log, D_skip, p_y);

    // 7. out_proj + residual
    gemm_mma_kernel<128, 2, 1><<<dim3(DMODEL / 128, MROWS / 128), 256, SMEM_GEMM(128)>>>(
        p_y, DINCH, out_w, DINCH, nullptr, x, out, DMODEL, DINCH);
}